// round 13
// baseline (speedup 1.0000x reference)
#include <cuda_runtime.h>
#include <cuda_fp16.h>
#include <cstdint>

#define NB   8192
#define NFLD 64
#define DDIM 128

// ---------------- device globals (no allocation allowed) ----------------
__device__ __align__(16) __half g_Sh [(size_t)NB * NFLD * NFLD];   // S fp16, 64 MB
__device__ __align__(16) __half g_Rh [(size_t)NB * NFLD * DDIM];   // R = F@Qw^T fp16, 128 MB
__device__ __align__(16) __half g_Wth[(size_t)NFLD * DDIM * NFLD]; // Wt[i][d][j] fp16
__device__ __align__(16) __half g_Kwh[DDIM * DDIM];                // fp16 K_w[e][d]
__device__ __align__(16) __half g_Qwh[DDIM * DDIM];                // fp16 Q_w[e][d]

// ---------------- helpers ----------------
__device__ __forceinline__ uint32_t smem_u32(const void* p) {
    uint32_t a;
    asm("{ .reg .u64 t; cvta.to.shared.u64 t, %1; cvt.u32.u64 %0, t; }"
        : "=r"(a) : "l"(p));
    return a;
}
__device__ __forceinline__ unsigned pk(float a, float b) {
    __half2 h = __floats2half2_rn(a, b);
    return *reinterpret_cast<unsigned*>(&h);
}
__device__ __forceinline__ uint4 cvt8(float4 a, float4 b) {
    return make_uint4(pk(a.x, a.y), pk(a.z, a.w), pk(b.x, b.y), pk(b.z, b.w));
}
__device__ __forceinline__ void ldsm4(uint32_t* r, uint32_t addr) {
    asm volatile("ldmatrix.sync.aligned.m8n8.x4.shared.b16 {%0,%1,%2,%3}, [%4];"
                 : "=r"(r[0]), "=r"(r[1]), "=r"(r[2]), "=r"(r[3]) : "r"(addr));
}
__device__ __forceinline__ void mma16(float* c, const uint32_t* a, const uint32_t* b) {
    asm volatile("mma.sync.aligned.m16n8k16.row.col.f32.f16.f16.f32 "
                 "{%0,%1,%2,%3},{%4,%5,%6,%7},{%8,%9},{%0,%1,%2,%3};"
                 : "+f"(c[0]), "+f"(c[1]), "+f"(c[2]), "+f"(c[3])
                 : "r"(a[0]), "r"(a[1]), "r"(a[2]), "r"(a[3]), "r"(b[0]), "r"(b[1]));
}
__device__ __forceinline__ uint32_t lda(uint32_t base, int ld, int row0, int colh, int lane) {
    return base + 2u * (uint32_t)((row0 + (lane & 15)) * ld + colh + ((lane >> 4) << 3));
}
__device__ __forceinline__ uint32_t ldb(uint32_t base, int ld, int n0, int k0, int lane) {
    int row  = n0 + ((lane >> 4) << 3) + (lane & 7);
    int koff = ((lane >> 3) & 1) << 3;
    return base + 2u * (uint32_t)(row * ld + k0 + koff);
}
__device__ __forceinline__ void dumph(char* smb, int ld, int row, int col, const float* c) {
    *reinterpret_cast<unsigned*>(smb + 2 * (row * ld + col))       = pk(c[0], c[1]);
    *reinterpret_cast<unsigned*>(smb + 2 * ((row + 8) * ld + col)) = pk(c[2], c[3]);
}
// cp.async 16B global -> shared
__device__ __forceinline__ void cpa16(uint32_t saddr, const void* g) {
    asm volatile("cp.async.cg.shared.global [%0], [%1], 16;" :: "r"(saddr), "l"(g));
}
#define CPA_COMMIT() asm volatile("cp.async.commit_group;" ::: "memory")
#define CPA_WAIT(n)  asm volatile("cp.async.wait_group %0;" :: "n"(n) : "memory")

// ---------------- prep: fp16 weights + W transpose ----------------
__global__ void prep(const float* __restrict__ W, const float* __restrict__ Kw,
                     const float* __restrict__ Qw) {
    extern __shared__ __half th[];            // 64 x 136
    const int bid = blockIdx.x, tid = threadIdx.x;
    if (bid < 64) {
        const float4* W4 = reinterpret_cast<const float4*>(W) + (size_t)bid * 2048;
        #pragma unroll
        for (int it = 0; it < 8; it++) {
            int x = tid + it * 256;
            float4 v = W4[x];
            int j = x >> 5, d4 = (x & 31) * 4;
            __half* p = th + j * 136 + d4;
            p[0] = __float2half_rn(v.x); p[1] = __float2half_rn(v.y);
            p[2] = __float2half_rn(v.z); p[3] = __float2half_rn(v.w);
        }
        __syncthreads();
        #pragma unroll
        for (int it = 0; it < 4; it++) {
            int x = tid + it * 256;
            int d = x >> 3, j0 = (x & 7) * 8;
            __half tmp[8];
            #pragma unroll
            for (int t = 0; t < 8; t++) tmp[t] = th[(j0 + t) * 136 + d];
            reinterpret_cast<uint4*>(g_Wth)[(size_t)bid * 1024 + x] =
                *reinterpret_cast<uint4*>(tmp);
        }
    } else {
        const float* src = (bid == 64) ? Kw : Qw;
        __half2* dst = reinterpret_cast<__half2*>((bid == 64) ? g_Kwh : g_Qwh);
        #pragma unroll
        for (int it = 0; it < 16; it++) {
            int x = tid + it * 256;
            float4 v = reinterpret_cast<const float4*>(src)[x];
            dst[2 * x]     = __floats2half2_rn(v.x, v.y);
            dst[2 * x + 1] = __floats2half2_rn(v.z, v.w);
        }
    }
}

// ---------------- k1: per 2 batches — Kf, then fused {S(diag) + R} ----------------
// smem: smF [128][136] (F2 fp16)
//       smB [128][136] (Kw -> Kf -> S-stage [128][72])
//       smKf[128][136] (Qw prefetch -> R-stage)
#define K1_OFF_B  34816
#define K1_OFF_KF 69632
#define K1_SMEM   104448

__global__ void __launch_bounds__(256, 2) k1(const float* __restrict__ F) {
    extern __shared__ char sm[];
    char* smF  = sm;
    char* smB  = sm + K1_OFF_B;
    char* smKf = sm + K1_OFF_KF;
    const uint32_t ubF = smem_u32(smF), ubB = smem_u32(smB), ubKf = smem_u32(smKf);
    const int tid = threadIdx.x, wid = tid >> 5, lane = tid & 31;
    const int wm = wid >> 2, wn = wid & 3;
    const int r0 = lane >> 2, cO = 2 * (lane & 3);
    const int bp = blockIdx.x;

    // ---- prefetch Kw -> smB (group old), Qw -> smKf; stage F (cvt) ----
    #pragma unroll
    for (int it = 0; it < 8; it++) {
        int x = tid + it * 256;                    // 0..2047 uint4
        uint32_t d = 2u * (uint32_t)((x >> 4) * 136 + (x & 15) * 8);
        cpa16(ubB + d, reinterpret_cast<const uint4*>(g_Kwh) + x);
    }
    CPA_COMMIT();                                  // group: Kw
    #pragma unroll
    for (int it = 0; it < 8; it++) {
        int x = tid + it * 256;
        uint32_t d = 2u * (uint32_t)((x >> 4) * 136 + (x & 15) * 8);
        cpa16(ubKf + d, reinterpret_cast<const uint4*>(g_Qwh) + x);
    }
    CPA_COMMIT();                                  // group: Qw
    {
        const float4* F4 = reinterpret_cast<const float4*>(F) + (size_t)bp * 4096;
        #pragma unroll
        for (int it = 0; it < 8; it++) {
            int x = tid + it * 256;
            int u = x >> 4, c8 = x & 15;
            float4 a = F4[u * 32 + c8 * 2], b = F4[u * 32 + c8 * 2 + 1];
            *reinterpret_cast<uint4*>(smF + 2 * (u * 136 + c8 * 8)) = cvt8(a, b);
        }
    }
    CPA_WAIT(1);                                   // Kw resident (Qw may fly)
    __syncthreads();

    // ---- GEMM1: Kf = F2 @ Kw^T (128x128, K=128) ----
    float accK[4][4][4];
    #pragma unroll
    for (int mt = 0; mt < 4; mt++)
        #pragma unroll
        for (int nt = 0; nt < 4; nt++)
            #pragma unroll
            for (int q = 0; q < 4; q++) accK[mt][nt][q] = 0.f;
    #pragma unroll
    for (int ks = 0; ks < 8; ks++) {
        uint32_t a[4][4], bq[2][4];
        #pragma unroll
        for (int mt = 0; mt < 4; mt++)
            ldsm4(a[mt], lda(ubF, 136, wm * 64 + mt * 16, ks * 16, lane));
        #pragma unroll
        for (int bt = 0; bt < 2; bt++)
            ldsm4(bq[bt], ldb(ubB, 136, wn * 32 + bt * 16, ks * 16, lane));
        #pragma unroll
        for (int mt = 0; mt < 4; mt++)
            #pragma unroll
            for (int nt = 0; nt < 4; nt++)
                mma16(accK[mt][nt], a[mt], &bq[nt >> 1][(nt & 1) * 2]);
    }
    __syncthreads();                               // Kw reads done

    // ---- dump Kf -> smB (over Kw) ----
    #pragma unroll
    for (int mt = 0; mt < 4; mt++)
        #pragma unroll
        for (int nt = 0; nt < 4; nt++)
            dumph(smB, 136, wm * 64 + mt * 16 + r0, wn * 32 + nt * 8 + cO, accK[mt][nt]);
    CPA_WAIT(0);                                   // Qw resident
    __syncthreads();

    // ---- FUSED: GEMM2 (S diag) + GEMMR, shared A-fragments ----
    // warp (wm,wn): S for batch wm, j-cols wn*16..+15; R rows wm*64..+63, cols wn*32..+31
    float accS[4][2][4];
    float accR[4][4][4];
    #pragma unroll
    for (int mt = 0; mt < 4; mt++) {
        #pragma unroll
        for (int nt = 0; nt < 2; nt++)
            #pragma unroll
            for (int q = 0; q < 4; q++) accS[mt][nt][q] = 0.f;
        #pragma unroll
        for (int nt = 0; nt < 4; nt++)
            #pragma unroll
            for (int q = 0; q < 4; q++) accR[mt][nt][q] = 0.f;
    }
    #pragma unroll
    for (int ks = 0; ks < 8; ks++) {
        uint32_t a[4][4];
        #pragma unroll
        for (int mt = 0; mt < 4; mt++)
            ldsm4(a[mt], lda(ubF, 136, wm * 64 + mt * 16, ks * 16, lane));
        {   // S: B = Kf rows (batch-diag) wm*64 + wn*16, 16 rows
            uint32_t bk[4];
            ldsm4(bk, ldb(ubB, 136, wm * 64 + wn * 16, ks * 16, lane));
            #pragma unroll
            for (int mt = 0; mt < 4; mt++) {
                mma16(accS[mt][0], a[mt], &bk[0]);
                mma16(accS[mt][1], a[mt], &bk[2]);
            }
        }
        {   // R n-half 0: B = Qw rows wn*32
            uint32_t bq[4];
            ldsm4(bq, ldb(ubKf, 136, wn * 32, ks * 16, lane));
            #pragma unroll
            for (int mt = 0; mt < 4; mt++) {
                mma16(accR[mt][0], a[mt], &bq[0]);
                mma16(accR[mt][1], a[mt], &bq[2]);
            }
        }
        {   // R n-half 1: B = Qw rows wn*32+16
            uint32_t bq[4];
            ldsm4(bq, ldb(ubKf, 136, wn * 32 + 16, ks * 16, lane));
            #pragma unroll
            for (int mt = 0; mt < 4; mt++) {
                mma16(accR[mt][2], a[mt], &bq[0]);
                mma16(accR[mt][3], a[mt], &bq[2]);
            }
        }
    }
    __syncthreads();                               // Kf + Qw reads done

    // ---- dump S -> smB stage [128][72]; dump R -> smKf (over Qw) ----
    #pragma unroll
    for (int mt = 0; mt < 4; mt++)
        #pragma unroll
        for (int nt = 0; nt < 2; nt++)
            dumph(smB, 72, wm * 64 + mt * 16 + r0, wn * 16 + nt * 8 + cO, accS[mt][nt]);
    #pragma unroll
    for (int mt = 0; mt < 4; mt++)
        #pragma unroll
        for (int nt = 0; nt < 4; nt++)
            dumph(smKf, 136, wm * 64 + mt * 16 + r0, wn * 32 + nt * 8 + cO, accR[mt][nt]);
    __syncthreads();

    // ---- bulk store S and R ----
    #pragma unroll
    for (int it = 0; it < 4; it++) {
        int x = tid + it * 256;
        int bt = x >> 9, rem = x & 511, i = rem >> 3, c8 = rem & 7;
        uint4 v = *reinterpret_cast<const uint4*>(smB + 2 * ((bt * 64 + i) * 72 + c8 * 8));
        reinterpret_cast<uint4*>(g_Sh)[(size_t)bp * 1024 + bt * 512 + i * 8 + c8] = v;
    }
    #pragma unroll
    for (int it = 0; it < 8; it++) {
        int x = tid + it * 256;
        uint4 v = *reinterpret_cast<const uint4*>(smKf + 2 * ((x >> 4) * 136 + (x & 15) * 8));
        reinterpret_cast<uint4*>(g_Rh)[(size_t)bp * 2048 + x] = v;
    }
}

// ---------------- k2: out[:,i,:] = S[:,i,:] @ Wt[i] + R[:,i,:] ----------------
#define K2_OFF_W 18432
#define K2_OFF_R 36864
#define K2_SMEM  71680

__global__ void __launch_bounds__(256, 2) k2(float* __restrict__ out) {
    extern __shared__ char sm[];
    char* smS = sm;
    char* smW = sm + K2_OFF_W;
    char* smR = sm + K2_OFF_R;
    const uint32_t ubS = smem_u32(smS), ubW = smem_u32(smW), ubR = smem_u32(smR);
    const int tid = threadIdx.x, wid = tid >> 5, lane = tid & 31;
    const int wm = wid >> 2, wn = wid & 3;
    const int r0 = lane >> 2, cO = 2 * (lane & 3);
    const int i = blockIdx.y;
    const int b0 = blockIdx.x * 128;

    // ---- cp.async stage S, Wt[i], R ----
    #pragma unroll
    for (int it = 0; it < 4; it++) {
        int x = tid + it * 256;                    // 0..1023
        int u = x >> 3, c8 = x & 7;
        cpa16(ubS + 2u * (uint32_t)(u * 72 + c8 * 8),
              reinterpret_cast<const uint4*>(g_Sh) + ((size_t)(b0 + u) * NFLD + i) * 8 + c8);
        cpa16(ubW + 2u * (uint32_t)(u * 72 + c8 * 8),
              reinterpret_cast<const uint4*>(g_Wth) + (size_t)i * 1024 + x);
    }
    #pragma unroll
    for (int it = 0; it < 8; it++) {
        int x = tid + it * 256;                    // 0..2047
        int r = x >> 4, c8 = x & 15;
        cpa16(ubR + 2u * (uint32_t)(r * 136 + c8 * 8),
              reinterpret_cast<const uint4*>(g_Rh) + ((size_t)(b0 + r) * NFLD + i) * 16 + c8);
    }
    CPA_COMMIT();
    CPA_WAIT(0);
    __syncthreads();

    float acc[4][4][4];
    #pragma unroll
    for (int mt = 0; mt < 4; mt++)
        #pragma unroll
        for (int nt = 0; nt < 4; nt++)
            #pragma unroll
            for (int q = 0; q < 4; q++) acc[mt][nt][q] = 0.f;
    #pragma unroll
    for (int ks = 0; ks < 4; ks++) {
        uint32_t a[4][4], bq[2][4];
        #pragma unroll
        for (int mt = 0; mt < 4; mt++)
            ldsm4(a[mt], lda(ubS, 72, wm * 64 + mt * 16, ks * 16, lane));
        #pragma unroll
        for (int bt = 0; bt < 2; bt++)
            ldsm4(bq[bt], ldb(ubW, 72, wn * 32 + bt * 16, ks * 16, lane));
        #pragma unroll
        for (int mt = 0; mt < 4; mt++)
            #pragma unroll
            for (int nt = 0; nt < 4; nt++)
                mma16(acc[mt][nt], a[mt], &bq[nt >> 1][(nt & 1) * 2]);
    }

    // ---- add residual R, then DIRECT global stores (no smem epilogue) ----
    #pragma unroll
    for (int mt = 0; mt < 4; mt++) {
        int row = wm * 64 + mt * 16 + r0;
        #pragma unroll
        for (int nt = 0; nt < 4; nt++) {
            int col = wn * 32 + nt * 8 + cO;
            __half2 h0 = *reinterpret_cast<const __half2*>(smR + 2 * (row * 136 + col));
            __half2 h1 = *reinterpret_cast<const __half2*>(smR + 2 * ((row + 8) * 136 + col));
            float2 f0 = __half22float2(h0), f1 = __half22float2(h1);
            float* o0 = out + ((size_t)(b0 + row) * NFLD + i) * DDIM + col;
            float* o1 = out + ((size_t)(b0 + row + 8) * NFLD + i) * DDIM + col;
            *reinterpret_cast<float2*>(o0) =
                make_float2(acc[mt][nt][0] + f0.x, acc[mt][nt][1] + f0.y);
            *reinterpret_cast<float2*>(o1) =
                make_float2(acc[mt][nt][2] + f1.x, acc[mt][nt][3] + f1.y);
        }
    }
}

// ---------------- launch ----------------
extern "C" void kernel_launch(void* const* d_in, const int* in_sizes, int n_in,
                              void* d_out, int out_size) {
    const float* F  = (const float*)d_in[0];
    const float* W  = (const float*)d_in[1];
    const float* Kw = (const float*)d_in[2];
    const float* Qw = (const float*)d_in[3];
    float* out = (float*)d_out;

    cudaFuncSetAttribute(prep, cudaFuncAttributeMaxDynamicSharedMemorySize, 17408);
    cudaFuncSetAttribute(k1,   cudaFuncAttributeMaxDynamicSharedMemorySize, K1_SMEM);
    cudaFuncSetAttribute(k2,   cudaFuncAttributeMaxDynamicSharedMemorySize, K2_SMEM);

    prep<<<66, 256, 17408>>>(W, Kw, Qw);
    k1<<<NB / 2, 256, K1_SMEM>>>(F);
    dim3 g2(NB / 128, NFLD);
    k2<<<g2, 256, K2_SMEM>>>(out);
}

// round 14
// speedup vs baseline: 1.2065x; 1.2065x over previous
#include <cuda_runtime.h>
#include <cuda_fp16.h>
#include <cstdint>

#define NB   8192
#define NFLD 64
#define DDIM 128

// ---------------- device globals (no allocation allowed) ----------------
__device__ __align__(16) __half g_Sh [(size_t)NB * NFLD * NFLD];   // S fp16, 64 MB
__device__ __align__(16) __half g_Fh [(size_t)NB * NFLD * DDIM];   // fp16(F), 128 MB
__device__ __align__(16) __half g_Wth[(size_t)NFLD * DDIM * NFLD]; // Wt[i][d][j] fp16
__device__ __align__(16) __half g_Kwh[DDIM * DDIM];                // fp16 K_w[e][d]
__device__ __align__(16) __half g_Qwh[DDIM * DDIM];                // fp16 Q_w[e][d]

// ---------------- helpers ----------------
__device__ __forceinline__ uint32_t smem_u32(const void* p) {
    uint32_t a;
    asm("{ .reg .u64 t; cvta.to.shared.u64 t, %1; cvt.u32.u64 %0, t; }"
        : "=r"(a) : "l"(p));
    return a;
}
__device__ __forceinline__ unsigned pk(float a, float b) {
    __half2 h = __floats2half2_rn(a, b);
    return *reinterpret_cast<unsigned*>(&h);
}
__device__ __forceinline__ uint4 cvt8(float4 a, float4 b) {
    return make_uint4(pk(a.x, a.y), pk(a.z, a.w), pk(b.x, b.y), pk(b.z, b.w));
}
__device__ __forceinline__ void ldsm4(uint32_t* r, uint32_t addr) {
    asm volatile("ldmatrix.sync.aligned.m8n8.x4.shared.b16 {%0,%1,%2,%3}, [%4];"
                 : "=r"(r[0]), "=r"(r[1]), "=r"(r[2]), "=r"(r[3]) : "r"(addr));
}
__device__ __forceinline__ void mma16(float* c, const uint32_t* a, const uint32_t* b) {
    asm volatile("mma.sync.aligned.m16n8k16.row.col.f32.f16.f16.f32 "
                 "{%0,%1,%2,%3},{%4,%5,%6,%7},{%8,%9},{%0,%1,%2,%3};"
                 : "+f"(c[0]), "+f"(c[1]), "+f"(c[2]), "+f"(c[3])
                 : "r"(a[0]), "r"(a[1]), "r"(a[2]), "r"(a[3]), "r"(b[0]), "r"(b[1]));
}
__device__ __forceinline__ uint32_t lda(uint32_t base, int ld, int row0, int colh, int lane) {
    return base + 2u * (uint32_t)((row0 + (lane & 15)) * ld + colh + ((lane >> 4) << 3));
}
__device__ __forceinline__ uint32_t ldb(uint32_t base, int ld, int n0, int k0, int lane) {
    int row  = n0 + ((lane >> 4) << 3) + (lane & 7);
    int koff = ((lane >> 3) & 1) << 3;
    return base + 2u * (uint32_t)(row * ld + k0 + koff);
}
__device__ __forceinline__ void dumph(char* smb, int ld, int row, int col, const float* c) {
    *reinterpret_cast<unsigned*>(smb + 2 * (row * ld + col))       = pk(c[0], c[1]);
    *reinterpret_cast<unsigned*>(smb + 2 * ((row + 8) * ld + col)) = pk(c[2], c[3]);
}
// cp.async 16B global -> shared
__device__ __forceinline__ void cpa16(uint32_t saddr, const void* g) {
    asm volatile("cp.async.cg.shared.global [%0], [%1], 16;" :: "r"(saddr), "l"(g));
}
#define CPA_COMMIT() asm volatile("cp.async.commit_group;" ::: "memory")
#define CPA_WAIT(n)  asm volatile("cp.async.wait_group %0;" :: "n"(n) : "memory")

// ---------------- prep: fp16 weights + W transpose ----------------
__global__ void prep(const float* __restrict__ W, const float* __restrict__ Kw,
                     const float* __restrict__ Qw) {
    extern __shared__ __half th[];            // 64 x 136
    const int bid = blockIdx.x, tid = threadIdx.x;
    if (bid < 64) {
        const float4* W4 = reinterpret_cast<const float4*>(W) + (size_t)bid * 2048;
        #pragma unroll
        for (int it = 0; it < 8; it++) {
            int x = tid + it * 256;
            float4 v = W4[x];
            int j = x >> 5, d4 = (x & 31) * 4;
            __half* p = th + j * 136 + d4;
            p[0] = __float2half_rn(v.x); p[1] = __float2half_rn(v.y);
            p[2] = __float2half_rn(v.z); p[3] = __float2half_rn(v.w);
        }
        __syncthreads();
        #pragma unroll
        for (int it = 0; it < 4; it++) {
            int x = tid + it * 256;
            int d = x >> 3, j0 = (x & 7) * 8;
            __half tmp[8];
            #pragma unroll
            for (int t = 0; t < 8; t++) tmp[t] = th[(j0 + t) * 136 + d];
            reinterpret_cast<uint4*>(g_Wth)[(size_t)bid * 1024 + x] =
                *reinterpret_cast<uint4*>(tmp);
        }
    } else {
        const float* src = (bid == 64) ? Kw : Qw;
        __half2* dst = reinterpret_cast<__half2*>((bid == 64) ? g_Kwh : g_Qwh);
        #pragma unroll
        for (int it = 0; it < 16; it++) {
            int x = tid + it * 256;
            float4 v = reinterpret_cast<const float4*>(src)[x];
            dst[2 * x]     = __floats2half2_rn(v.x, v.y);
            dst[2 * x + 1] = __floats2half2_rn(v.z, v.w);
        }
    }
}

// ---------------- k1: per 2 batches — Kf = F2@Kw^T, S = diag(F2@Kf^T), store fp16(F) ----------------
// smem: smF [128][136] fp16 (F2), smB [128][136] (Kw -> Kf), smSt [128][72] (S stage)
#define K1_OFF_B  34816
#define K1_OFF_ST 69632
#define K1_SMEM   88064

__global__ void __launch_bounds__(256, 2) k1(const float* __restrict__ F) {
    extern __shared__ char sm[];
    char* smF  = sm;
    char* smB  = sm + K1_OFF_B;
    char* smSt = sm + K1_OFF_ST;
    const uint32_t ubF = smem_u32(smF), ubB = smem_u32(smB);
    const int tid = threadIdx.x, wid = tid >> 5, lane = tid & 31;
    const int wm = wid >> 2, wn = wid & 3;
    const int r0 = lane >> 2, cO = 2 * (lane & 3);
    const int bp = blockIdx.x;

    // ---- prefetch Kw -> smB; stage F (f32 -> fp16) -> smF ----
    #pragma unroll
    for (int it = 0; it < 8; it++) {
        int x = tid + it * 256;                    // 0..2047 uint4
        uint32_t d = 2u * (uint32_t)((x >> 4) * 136 + (x & 15) * 8);
        cpa16(ubB + d, reinterpret_cast<const uint4*>(g_Kwh) + x);
    }
    CPA_COMMIT();
    {
        const float4* F4 = reinterpret_cast<const float4*>(F) + (size_t)bp * 4096;
        #pragma unroll
        for (int it = 0; it < 8; it++) {
            int x = tid + it * 256;
            int u = x >> 4, c8 = x & 15;
            float4 a = F4[u * 32 + c8 * 2], b = F4[u * 32 + c8 * 2 + 1];
            *reinterpret_cast<uint4*>(smF + 2 * (u * 136 + c8 * 8)) = cvt8(a, b);
        }
    }
    CPA_WAIT(0);
    __syncthreads();

    // ---- GEMM1: Kf = F2 @ Kw^T (128x128, K=128) ----
    float accK[4][4][4];
    #pragma unroll
    for (int mt = 0; mt < 4; mt++)
        #pragma unroll
        for (int nt = 0; nt < 4; nt++)
            #pragma unroll
            for (int q = 0; q < 4; q++) accK[mt][nt][q] = 0.f;
    #pragma unroll
    for (int ks = 0; ks < 8; ks++) {
        uint32_t a[4][4], bq[2][4];
        #pragma unroll
        for (int mt = 0; mt < 4; mt++)
            ldsm4(a[mt], lda(ubF, 136, wm * 64 + mt * 16, ks * 16, lane));
        #pragma unroll
        for (int bt = 0; bt < 2; bt++)
            ldsm4(bq[bt], ldb(ubB, 136, wn * 32 + bt * 16, ks * 16, lane));
        #pragma unroll
        for (int mt = 0; mt < 4; mt++)
            #pragma unroll
            for (int nt = 0; nt < 4; nt++)
                mma16(accK[mt][nt], a[mt], &bq[nt >> 1][(nt & 1) * 2]);
    }
    __syncthreads();                               // Kw reads done

    // ---- dump Kf -> smB (over Kw) ----
    #pragma unroll
    for (int mt = 0; mt < 4; mt++)
        #pragma unroll
        for (int nt = 0; nt < 4; nt++)
            dumph(smB, 136, wm * 64 + mt * 16 + r0, wn * 32 + nt * 8 + cO, accK[mt][nt]);
    __syncthreads();

    // ---- GEMM2: S diag blocks (per batch 64x64, K=128) ----
    float accS[2][4][4];
    #pragma unroll
    for (int mt = 0; mt < 2; mt++)
        #pragma unroll
        for (int nt = 0; nt < 4; nt++)
            #pragma unroll
            for (int q = 0; q < 4; q++) accS[mt][nt][q] = 0.f;
    const int h = wid >> 2, ww = wid & 3;
    const int m0  = h * 64 + (ww & 1) * 32;        // i rows (batch-stacked)
    const int n0j = h * 64 + (ww >> 1) * 32;       // Kf rows (batch-stacked)
    #pragma unroll
    for (int ks = 0; ks < 8; ks++) {
        uint32_t a2[2][4], b2[2][4];
        #pragma unroll
        for (int mt = 0; mt < 2; mt++)
            ldsm4(a2[mt], lda(ubF, 136, m0 + mt * 16, ks * 16, lane));
        #pragma unroll
        for (int bt = 0; bt < 2; bt++)
            ldsm4(b2[bt], ldb(ubB, 136, n0j + bt * 16, ks * 16, lane));
        #pragma unroll
        for (int mt = 0; mt < 2; mt++)
            #pragma unroll
            for (int nt = 0; nt < 4; nt++)
                mma16(accS[mt][nt], a2[mt], &b2[nt >> 1][(nt & 1) * 2]);
    }

    // ---- dump S -> smSt [128][72] (fresh region, no WAR hazard) ----
    #pragma unroll
    for (int mt = 0; mt < 2; mt++)
        #pragma unroll
        for (int nt = 0; nt < 4; nt++)
            dumph(smSt, 72, m0 + mt * 16 + r0, (ww >> 1) * 32 + nt * 8 + cO, accS[mt][nt]);
    __syncthreads();

    // ---- bulk store S (from smSt) and fp16(F) (from smF) ----
    #pragma unroll
    for (int it = 0; it < 4; it++) {
        int x = tid + it * 256;                    // 0..1023 uint4
        int bt = x >> 9, rem = x & 511, i = rem >> 3, c8 = rem & 7;
        uint4 v = *reinterpret_cast<const uint4*>(smSt + 2 * ((bt * 64 + i) * 72 + c8 * 8));
        reinterpret_cast<uint4*>(g_Sh)[(size_t)bp * 1024 + bt * 512 + i * 8 + c8] = v;
    }
    #pragma unroll
    for (int it = 0; it < 8; it++) {
        int x = tid + it * 256;                    // 0..2047 uint4
        uint4 v = *reinterpret_cast<const uint4*>(smF + 2 * ((x >> 4) * 136 + (x & 15) * 8));
        reinterpret_cast<uint4*>(g_Fh)[(size_t)bp * 2048 + x] = v;
    }
}

// ---------------- k2: out[:,i,:] = S[:,i,:]@Wt[i] + Fh[:,i,:]@Qw^T ----------------
// smem: smS [128][72], smW [128][72], smFh [128][136], smQ [128][136]
#define K2_OFF_W 18432
#define K2_OFF_F 36864
#define K2_OFF_Q 71680
#define K2_SMEM  106496

__global__ void __launch_bounds__(256, 2) k2(float* __restrict__ out) {
    extern __shared__ char sm[];
    char* smS  = sm;
    char* smW  = sm + K2_OFF_W;
    char* smFh = sm + K2_OFF_F;
    char* smQ  = sm + K2_OFF_Q;
    const uint32_t ubS = smem_u32(smS), ubW = smem_u32(smW);
    const uint32_t ubFh = smem_u32(smFh), ubQ = smem_u32(smQ);
    const int tid = threadIdx.x, wid = tid >> 5, lane = tid & 31;
    const int wm = wid >> 2, wn = wid & 3;
    const int r0 = lane >> 2, cO = 2 * (lane & 3);
    const int i = blockIdx.y;
    const int b0 = blockIdx.x * 128;

    // ---- cp.async stage S, Wt[i], Fh rows, Qw ----
    #pragma unroll
    for (int it = 0; it < 4; it++) {
        int x = tid + it * 256;                    // 0..1023
        int u = x >> 3, c8 = x & 7;
        cpa16(ubS + 2u * (uint32_t)(u * 72 + c8 * 8),
              reinterpret_cast<const uint4*>(g_Sh) + ((size_t)(b0 + u) * NFLD + i) * 8 + c8);
        cpa16(ubW + 2u * (uint32_t)(u * 72 + c8 * 8),
              reinterpret_cast<const uint4*>(g_Wth) + (size_t)i * 1024 + x);
    }
    #pragma unroll
    for (int it = 0; it < 8; it++) {
        int x = tid + it * 256;                    // 0..2047
        int u = x >> 4, c8 = x & 15;
        cpa16(ubFh + 2u * (uint32_t)(u * 136 + c8 * 8),
              reinterpret_cast<const uint4*>(g_Fh) + ((size_t)(b0 + u) * NFLD + i) * 16 + c8);
        cpa16(ubQ + 2u * (uint32_t)(u * 136 + c8 * 8),
              reinterpret_cast<const uint4*>(g_Qwh) + x);
    }
    CPA_COMMIT();
    CPA_WAIT(0);
    __syncthreads();

    float acc[4][4][4];
    #pragma unroll
    for (int mt = 0; mt < 4; mt++)
        #pragma unroll
        for (int nt = 0; nt < 4; nt++)
            #pragma unroll
            for (int q = 0; q < 4; q++) acc[mt][nt][q] = 0.f;

    // ---- Phase A: S @ Wt[i]  (K = 64) ----
    #pragma unroll
    for (int ks = 0; ks < 4; ks++) {
        uint32_t a[4][4], bq[2][4];
        #pragma unroll
        for (int mt = 0; mt < 4; mt++)
            ldsm4(a[mt], lda(ubS, 72, wm * 64 + mt * 16, ks * 16, lane));
        #pragma unroll
        for (int bt = 0; bt < 2; bt++)
            ldsm4(bq[bt], ldb(ubW, 72, wn * 32 + bt * 16, ks * 16, lane));
        #pragma unroll
        for (int mt = 0; mt < 4; mt++)
            #pragma unroll
            for (int nt = 0; nt < 4; nt++)
                mma16(acc[mt][nt], a[mt], &bq[nt >> 1][(nt & 1) * 2]);
    }
    // ---- Phase B: Fh @ Qw^T  (K = 128) ----
    #pragma unroll
    for (int ks = 0; ks < 8; ks++) {
        uint32_t a[4][4], bq[2][4];
        #pragma unroll
        for (int mt = 0; mt < 4; mt++)
            ldsm4(a[mt], lda(ubFh, 136, wm * 64 + mt * 16, ks * 16, lane));
        #pragma unroll
        for (int bt = 0; bt < 2; bt++)
            ldsm4(bq[bt], ldb(ubQ, 136, wn * 32 + bt * 16, ks * 16, lane));
        #pragma unroll
        for (int mt = 0; mt < 4; mt++)
            #pragma unroll
            for (int nt = 0; nt < 4; nt++)
                mma16(acc[mt][nt], a[mt], &bq[nt >> 1][(nt & 1) * 2]);
    }

    // ---- direct global stores (8-float contiguous runs per lane-quad) ----
    #pragma unroll
    for (int mt = 0; mt < 4; mt++) {
        int row = wm * 64 + mt * 16 + r0;
        #pragma unroll
        for (int nt = 0; nt < 4; nt++) {
            int col = wn * 32 + nt * 8 + cO;
            float* o0 = out + ((size_t)(b0 + row) * NFLD + i) * DDIM + col;
            float* o1 = out + ((size_t)(b0 + row + 8) * NFLD + i) * DDIM + col;
            *reinterpret_cast<float2*>(o0) = make_float2(acc[mt][nt][0], acc[mt][nt][1]);
            *reinterpret_cast<float2*>(o1) = make_float2(acc[mt][nt][2], acc[mt][nt][3]);
        }
    }
}

// ---------------- launch ----------------
extern "C" void kernel_launch(void* const* d_in, const int* in_sizes, int n_in,
                              void* d_out, int out_size) {
    const float* F  = (const float*)d_in[0];
    const float* W  = (const float*)d_in[1];
    const float* Kw = (const float*)d_in[2];
    const float* Qw = (const float*)d_in[3];
    float* out = (float*)d_out;

    cudaFuncSetAttribute(prep, cudaFuncAttributeMaxDynamicSharedMemorySize, 17408);
    cudaFuncSetAttribute(k1,   cudaFuncAttributeMaxDynamicSharedMemorySize, K1_SMEM);
    cudaFuncSetAttribute(k2,   cudaFuncAttributeMaxDynamicSharedMemorySize, K2_SMEM);

    prep<<<66, 256, 17408>>>(W, Kw, Qw);
    k1<<<NB / 2, 256, K1_SMEM>>>(F);
    dim3 g2(NB / 128, NFLD);
    k2<<<g2, 256, K2_SMEM>>>(out);
}